// round 7
// baseline (speedup 1.0000x reference)
#include <cuda_runtime.h>
#include <cuda_fp16.h>
#include <cstdint>

#define Bdim 8
#define Ndim 512
#define Sdim 4096
#define Hdim 1024

#define BM 128
#define BN 128
#define BK 64
#define STAGES 3
#define NKITER (Sdim / BK)          // 64
#define NTHREADS 128

// fp16 SMEM tiles with padded rows (conflict-free ldmatrix groups)
#define A_ROW_B 144                  // 64 halves (128B) + 16B pad
#define B_ROW_B 272                  // 128 halves (256B) + 16B pad
#define A_STAGE_B (BM * A_ROW_B)     // 18432 B
#define B_STAGE_B (BK * B_ROW_B)     // 17408 B
#define STAGE_B   (A_STAGE_B + B_STAGE_B)   // 35840 B
#define DYN_SMEM  (STAGES * STAGE_B)        // 107520 B

// fp16 scratch (static device globals -- allowed scratch path)
__device__ __align__(16) __half g_doc_h[(size_t)Bdim * Sdim * Hdim];  // 67.1 MB
__device__ __align__(16) __half g_map_h[(size_t)Bdim * Ndim * Sdim];  // 33.6 MB

__device__ __forceinline__ uint32_t smem_u32(const void* p) {
    uint32_t a;
    asm("{ .reg .u64 t; cvta.to.shared.u64 t, %1; cvt.u32.u64 %0, t; }" : "=r"(a) : "l"(p));
    return a;
}
__device__ __forceinline__ void cp16(uint32_t sdst, const void* gsrc) {
    asm volatile("cp.async.cg.shared.global [%0], [%1], 16;" :: "r"(sdst), "l"(gsrc));
}
__device__ __forceinline__ uint32_t h2u(__half2 h) {
    return *reinterpret_cast<uint32_t*>(&h);
}

// ---------------- conversion pre-pass ----------------
__device__ __forceinline__ void cvt_body(const float* __restrict__ src,
                                         __half* __restrict__ dst, size_t n8) {
    size_t i = (size_t)blockIdx.x * blockDim.x + threadIdx.x;
    const size_t stride = (size_t)gridDim.x * blockDim.x;
    const float4* s4 = reinterpret_cast<const float4*>(src);
    uint4* d4 = reinterpret_cast<uint4*>(dst);
    for (; i < n8; i += stride) {
        const float4 v0 = s4[2 * i];
        const float4 v1 = s4[2 * i + 1];
        uint4 o;
        o.x = h2u(__floats2half2_rn(v0.x, v0.y));
        o.y = h2u(__floats2half2_rn(v0.z, v0.w));
        o.z = h2u(__floats2half2_rn(v1.x, v1.y));
        o.w = h2u(__floats2half2_rn(v1.z, v1.w));
        d4[i] = o;
    }
}
__global__ void __launch_bounds__(256) cvt_doc(const float* __restrict__ src) {
    cvt_body(src, g_doc_h, (size_t)Bdim * Sdim * Hdim / 8);
}
__global__ void __launch_bounds__(256) cvt_map(const float* __restrict__ src) {
    cvt_body(src, g_map_h, (size_t)Bdim * Ndim * Sdim / 8);
}

// ---------------- main GEMM ----------------
__global__ void __launch_bounds__(NTHREADS, 2)
mean_pool_mma(const float* __restrict__ lens,  // [B,N]
              float* __restrict__ out)         // [B,N,H]
{
    extern __shared__ char smraw[];

    const int tid  = threadIdx.x;
    const int lane = tid & 31;
    const int w    = tid >> 5;       // 4 warps
    const int wm   = w & 1;          // 2 warps along M (64 rows each)
    const int wn   = w >> 1;         // 2 warps along N (64 cols each)

    const int b  = blockIdx.z;
    const int m0 = blockIdx.y * BM;
    const int h0 = blockIdx.x * BN;

    const __half* Ag = g_map_h + (size_t)b * Ndim * Sdim + (size_t)m0 * Sdim;  // [BM, S]
    const __half* Bg = g_doc_h + (size_t)b * Sdim * Hdim + h0;                 // [S, BN]

    const uint32_t sbase = smem_u32(smraw);

    // async tile loader: A 128x64 halves (rows 144B), B 64x128 halves (rows 272B)
    auto load_stage = [&](int st, int k0) {
        const uint32_t abase = sbase + (uint32_t)(st * STAGE_B);
        const uint32_t bbase = abase + A_STAGE_B;
        #pragma unroll
        for (int i = 0; i < 8; i++) {          // A: 1024 16B-chunks
            const int c = tid + NTHREADS * i;
            const int m = c >> 3, q = c & 7;
            cp16(abase + (uint32_t)(m * A_ROW_B + q * 16),
                 Ag + (size_t)m * Sdim + k0 + q * 8);
        }
        #pragma unroll
        for (int i = 0; i < 8; i++) {          // B: 1024 16B-chunks
            const int c = tid + NTHREADS * i;
            const int k = c >> 4, q = c & 15;
            cp16(bbase + (uint32_t)(k * B_ROW_B + q * 16),
                 Bg + (size_t)(k0 + k) * Hdim + q * 8);
        }
    };

    float acc[4][8][4];
    #pragma unroll
    for (int i = 0; i < 4; i++)
        #pragma unroll
        for (int j = 0; j < 8; j++)
            #pragma unroll
            for (int r = 0; r < 4; r++)
                acc[i][j][r] = 0.0f;

    // prologue
    #pragma unroll
    for (int s = 0; s < STAGES - 1; s++) {
        load_stage(s, s * BK);
        asm volatile("cp.async.commit_group;");
    }

    // ldmatrix lane address components
    const int t8 = lane >> 3;        // 0..3 tile index within x4
    const int r8 = lane & 7;         // row within 8x8 tile
    const uint32_t a_lane_off =
        (uint32_t)(((t8 & 1) * 8 + r8) * A_ROW_B + (t8 >> 1) * 16);
    const uint32_t b_lane_off =
        (uint32_t)(((t8 & 1) * 8 + r8) * B_ROW_B + (t8 >> 1) * 16);

    uint32_t a[2][4][4];      // [buf][m16 tile][reg]
    uint32_t bfr[2][8][2];    // [buf][n8 tile][reg]

    auto load_frags = [&](int buf, uint32_t awarp, uint32_t bwarp, int kc) {
        #pragma unroll
        for (int i = 0; i < 4; i++) {
            const uint32_t addr = awarp + (uint32_t)(i * 16 * A_ROW_B + kc * 32);
            asm volatile(
                "ldmatrix.sync.aligned.m8n8.x4.shared.b16 {%0,%1,%2,%3}, [%4];"
                : "=r"(a[buf][i][0]), "=r"(a[buf][i][1]),
                  "=r"(a[buf][i][2]), "=r"(a[buf][i][3])
                : "r"(addr));
        }
        #pragma unroll
        for (int jt = 0; jt < 4; jt++) {
            const uint32_t addr = bwarp + (uint32_t)(kc * 16 * B_ROW_B + jt * 32);
            asm volatile(
                "ldmatrix.sync.aligned.m8n8.x4.trans.shared.b16 {%0,%1,%2,%3}, [%4];"
                : "=r"(bfr[buf][2 * jt][0]), "=r"(bfr[buf][2 * jt][1]),
                  "=r"(bfr[buf][2 * jt + 1][0]), "=r"(bfr[buf][2 * jt + 1][1])
                : "r"(addr));
        }
    };

    #pragma unroll 1
    for (int kt = 0; kt < NKITER; kt++) {
        asm volatile("cp.async.wait_group 1;" ::: "memory");
        __syncthreads();

        const int st = kt % STAGES;
        const uint32_t abase = sbase + (uint32_t)(st * STAGE_B);
        const uint32_t awarp = abase + (uint32_t)((wm * 64) * A_ROW_B) + a_lane_off;
        const uint32_t bwarp = abase + A_STAGE_B + (uint32_t)((wn * 64) * 2) + b_lane_off;

        load_frags(0, awarp, bwarp, 0);

        #pragma unroll
        for (int kc = 0; kc < 4; kc++) {       // four k=16 steps
            const int cur = kc & 1;
            if (kc + 1 < 4) load_frags(cur ^ 1, awarp, bwarp, kc + 1);
            #pragma unroll
            for (int i = 0; i < 4; i++)
                #pragma unroll
                for (int j = 0; j < 8; j++) {
                    asm volatile(
                        "mma.sync.aligned.m16n8k16.row.col.f32.f16.f16.f32 "
                        "{%0,%1,%2,%3}, {%4,%5,%6,%7}, {%8,%9}, {%0,%1,%2,%3};"
                        : "+f"(acc[i][j][0]), "+f"(acc[i][j][1]),
                          "+f"(acc[i][j][2]), "+f"(acc[i][j][3])
                        : "r"(a[cur][i][0]), "r"(a[cur][i][1]),
                          "r"(a[cur][i][2]), "r"(a[cur][i][3]),
                          "r"(bfr[cur][j][0]), "r"(bfr[cur][j][1]));
                }
        }

        const int ls = kt + STAGES - 1;
        if (ls < NKITER) load_stage(ls % STAGES, ls * BK);
        asm volatile("cp.async.commit_group;");
    }

    // epilogue: scale by 1/len, store float2 pairs
    const float* lb = lens + b * Ndim;
    const int gid = lane >> 2, tq = lane & 3;
    #pragma unroll
    for (int i = 0; i < 4; i++) {
        const int r0 = m0 + wm * 64 + i * 16 + gid;
        const int r1 = r0 + 8;
        const float inv0 = 1.0f / lb[r0];
        const float inv1 = 1.0f / lb[r1];
        float* o0 = out + (size_t)b * Ndim * Hdim + (size_t)r0 * Hdim + h0;
        float* o1 = out + (size_t)b * Ndim * Hdim + (size_t)r1 * Hdim + h0;
        #pragma unroll
        for (int j = 0; j < 8; j++) {
            const int h = wn * 64 + j * 8 + 2 * tq;
            *reinterpret_cast<float2*>(o0 + h) =
                make_float2(acc[i][j][0] * inv0, acc[i][j][1] * inv0);
            *reinterpret_cast<float2*>(o1 + h) =
                make_float2(acc[i][j][2] * inv1, acc[i][j][3] * inv1);
        }
    }
}

extern "C" void kernel_launch(void* const* d_in, const int* in_sizes, int n_in,
                              void* d_out, int out_size) {
    const float* doc  = (const float*)d_in[0];   // [8, 4096, 1024]
    const float* map  = (const float*)d_in[1];   // [8, 512, 4096]
    const float* lens = (const float*)d_in[2];   // [8, 512]
    float* out = (float*)d_out;                  // [8, 512, 1024]

    cvt_doc<<<2048, 256>>>(doc);
    cvt_map<<<1024, 256>>>(map);

    cudaFuncSetAttribute(mean_pool_mma, cudaFuncAttributeMaxDynamicSharedMemorySize, DYN_SMEM);
    dim3 grid(Hdim / BN, Ndim / BM, Bdim);   // (8, 4, 8) = 256 CTAs
    mean_pool_mma<<<grid, NTHREADS, DYN_SMEM>>>(lens, out);
}